// round 12
// baseline (speedup 1.0000x reference)
#include <cuda_runtime.h>

// ---------------------------------------------------------------------------
// Single fused kernel. out[p] = prod_l (1 - V[l,p]) * poly(p), V pseudo-Voigt.
// CTA = 676-px chunk (grid = 148 = one wave), BLOCK = 896 (28 warps).
//
// R12 (latency head/tail attack on the R11 structure):
//  - first stream strip (4x LDG.128) prefetched BEFORE LUT init + barrier
//  - poly coeffs pa/pb/pc loaded at kernel start, consumed in the epilogue
//  - warp-near uses one rcp per TWO lines (paired denominators)
// Hierarchy: CTA-far (4 nodes, cubic, inline in stream) / CTA-mid (16 nodes,
// piecewise cubic, warps 22..27) / warp-mid (3 nodes, quadratic) /
// warp-near exact. eta via 129-entry smem LUT on u = gw-sw.
// ---------------------------------------------------------------------------

#define BLOCK     896
#define NWARPS    28
#define CHUNK     676
#define NWIN      4.0f
#define AWIN      20.0f
#define WNWIN     4.0f
#define STASH     256
#define SMASK     255
#define LOG2E     1.4426950408889634f
#define FULLM     0xFFFFFFFFu

__device__ __forceinline__ float frcp(float x) {
    float r; asm("rcp.approx.ftz.f32 %0, %1;" : "=f"(r) : "f"(x)); return r;
}
__device__ __forceinline__ float fex2(float x) {
    float r; asm("ex2.approx.ftz.f32 %0, %1;" : "=f"(r) : "f"(x)); return r;
}
__device__ __forceinline__ float flg2(float x) {
    float r; asm("lg2.approx.ftz.f32 %0, %1;" : "=f"(r) : "f"(x)); return r;
}

__global__ void __launch_bounds__(BLOCK)
fused_kernel(const float* __restrict__ wl, int npix, int L,
             const float* __restrict__ lam,
             const float* __restrict__ amps,
             const float* __restrict__ sw,
             const float* __restrict__ gw,
             const float* __restrict__ pa,
             const float* __restrict__ pb,
             const float* __restrict__ pc,
             float* __restrict__ out) {
    __shared__ float  sLUT[129];
    __shared__ float4 sA[STASH];
    __shared__ float  sB[STASH];
    __shared__ float  sWredF[4 * NWARPS];
    __shared__ float  sS[4];
    __shared__ float  sMid[16];
    __shared__ int    sIdx[4];

    const int tid  = threadIdx.x;
    const int w    = tid >> 5, lane = tid & 31;
    const int p0   = blockIdx.x * CHUNK;
    const int cnt  = min(CHUNK, npix - p0);
    const int p    = p0 + tid;

    // ---- early loads: issue ASAP, consume much later ----
    const float wlp = wl[min(p, npix - 1)];
    const float cpa = pa[0], cpb = pb[0], cpc = pc[0];
    const float wlLo = wl[p0];
    const float wlHi = wl[p0 + cnt - 1];

    const int nq = L >> 2;
    float4 l4, a4, s4, g4;
    const bool act0 = tid < nq;
    if (act0) {
        l4 = ((const float4*)lam)[tid];
        a4 = ((const float4*)amps)[tid];
        s4 = ((const float4*)sw)[tid];
        g4 = ((const float4*)gw)[tid];
    }

    const float span = wlHi - wlLo;
    const float b0 = wlLo - AWIN, b1 = wlLo - NWIN;
    const float b2 = wlHi + NWIN, b3 = wlHi + AWIN;
    const float n1w = fmaf(span, 1.0f / 3.0f, wlLo);
    const float n2w = fmaf(span, 2.0f / 3.0f, wlLo);

    if (tid < 2) { sIdx[tid * 2] = 0x7FFFFFFF; sIdx[tid * 2 + 1] = -1; }
    if (tid < 129) {
        float u = fmaf((float)tid, 0.0375f, -2.4f);
        float r = 0.8492866f * fex2(u * LOG2E);           // fl/fg
        float P = 1.0f + r * (2.69269f + r * (2.42843f
                 + r * (4.47163f + r * (0.07842f + r))));
        float fr = r * fex2(-0.2f * flg2(P));             // fl/fwhm
        sLUT[tid] = fr * (1.36603f + fr * (-0.47719f + fr * 0.11116f));
    }
    __syncthreads();

    // ---- stream all lines: LUT constants + far sums + slot stash ----
    float S0 = 0.f, S1 = 0.f, S2 = 0.f, S3 = 0.f;

    auto body = [&](int l, float lc, float av, float swv, float gwv) {
        float fi = fmaf(gwv - swv, 26.6666667f, 64.0f);
        fi = fminf(fmaxf(fi, 0.0f), 127.99f);
        int   ii  = (int)fi;
        float fr8 = fi - (float)ii;
        float el  = sLUT[ii], eh = sLUT[ii + 1];
        float eta = fmaf(fr8, eh - el, el);

        float gamma = fex2(gwv * LOG2E);
        float ag    = fex2((av + gwv) * LOG2E);           // amp*gamma
        float g2 = gamma * gamma;
        float cl = ag * eta * 0.3183098862f;

        if (lc >= b0 && lc < b3) {
            float m  = -0.72134752f * fex2(-2.0f * swv * LOG2E);
            float cg = (1.0f - eta) * 0.39894228f * fex2((av - swv) * LOG2E);
            int slot = l & SMASK;
            sA[slot] = make_float4(lc, g2, cl, m);
            sB[slot] = cg;
            atomicMin(&sIdx[0], l);
            atomicMax(&sIdx[1], l);
            if (lc >= b1 && lc < b2) {
                atomicMin(&sIdx[2], l);
                atomicMax(&sIdx[3], l);
            }
        } else {
            float d0 = wlLo - lc, d1 = n1w - lc, d2 = n2w - lc, d3 = wlHi - lc;
            float e0 = fmaf(d0, d0, g2), e1 = fmaf(d1, d1, g2);
            float e2 = fmaf(d2, d2, g2), e3 = fmaf(d3, d3, g2);
            float p01 = e0 * e1, p23 = e2 * e3;
            float r   = frcp(p01 * p23);
            float r01 = r * p23, r23 = r * p01;
            S0 = fmaf(cl * e1, r01, S0);
            S1 = fmaf(cl * e0, r01, S1);
            S2 = fmaf(cl * e3, r23, S2);
            S3 = fmaf(cl * e2, r23, S3);
        }
    };

    if (act0) {
        int lb = tid * 4;
        body(lb + 0, l4.x, a4.x, s4.x, g4.x);
        body(lb + 1, l4.y, a4.y, s4.y, g4.y);
        body(lb + 2, l4.z, a4.z, s4.z, g4.z);
        body(lb + 3, l4.w, a4.w, s4.w, g4.w);
    }
    for (int t = tid + BLOCK; t < nq; t += BLOCK) {
        float4 lv = ((const float4*)lam)[t];
        float4 av = ((const float4*)amps)[t];
        float4 sv = ((const float4*)sw)[t];
        float4 gv = ((const float4*)gw)[t];
        int lb = t * 4;
        body(lb + 0, lv.x, av.x, sv.x, gv.x);
        body(lb + 1, lv.y, av.y, sv.y, gv.y);
        body(lb + 2, lv.z, av.z, sv.z, gv.z);
        body(lb + 3, lv.w, av.w, sv.w, gv.w);
    }
    for (int l = (nq << 2) + tid; l < L; l += BLOCK)
        body(l, lam[l], amps[l], sw[l], gw[l]);

    #pragma unroll
    for (int o = 16; o; o >>= 1) {
        S0 += __shfl_xor_sync(FULLM, S0, o);
        S1 += __shfl_xor_sync(FULLM, S1, o);
        S2 += __shfl_xor_sync(FULLM, S2, o);
        S3 += __shfl_xor_sync(FULLM, S3, o);
    }
    if (lane == 0) {
        sWredF[w]              = S0;
        sWredF[NWARPS + w]     = S1;
        sWredF[2 * NWARPS + w] = S2;
        sWredF[3 * NWARPS + w] = S3;
    }
    __syncthreads();

    int alo = sIdx[0], ahi = sIdx[1] + 1;
    if (ahi <= alo) { alo = 0; ahi = 0; }
    ahi = min(ahi, alo + STASH);
    int nlo = sIdx[2], nhi = sIdx[3] + 1;
    if (nhi <= nlo) { nlo = alo; nhi = alo; }
    nlo = max(nlo, alo); nhi = min(nhi, ahi);

    float prod = 1.0f;
    float M0 = 0.f, M1 = 0.f, M2 = 0.f;
    float x0n = 0.f, x2n = 1.f;

    if (w >= 22) {
        // ---- collective warps: far-node reduction + CTA-mid node sums ----
        if (w >= 24) {
            int node = w - 24;
            float v = (lane < NWARPS) ? sWredF[node * NWARPS + lane] : 0.f;
            #pragma unroll
            for (int o = 16; o; o >>= 1) v += __shfl_xor_sync(FULLM, v, o);
            if (lane == 0) sS[node] = v;
        }
        for (int node = w - 22; node < 16; node += 6) {
            float nodeM = fmaf((float)node, span * (1.0f / 15.0f), wlLo);
            float accM = 0.f;
            for (int j = alo + lane; j < nlo; j += 32) {
                float4 a = sA[j & SMASK];
                float d = nodeM - a.x;
                accM = fmaf(a.z, frcp(fmaf(d, d, a.y)), accM);
            }
            for (int j = nhi + lane; j < ahi; j += 32) {
                float4 a = sA[j & SMASK];
                float d = nodeM - a.x;
                accM = fmaf(a.z, frcp(fmaf(d, d, a.y)), accM);
            }
            #pragma unroll
            for (int o = 16; o; o >>= 1) accM += __shfl_xor_sync(FULLM, accM, o);
            if (lane == 0) sMid[node] = accM;
        }
    } else {
        // ---- pixel warps: classification + warp-mid + warp-near ----
        x0n = __shfl_sync(FULLM, wlp, 0);
        x2n = __shfl_sync(FULLM, wlp, 31);
        const float wLo = x0n - WNWIN, wHi = x2n + WNWIN;

        int glo = nhi, ghi = nlo;
        for (int base = nlo; base < nhi; base += 32) {
            int idx = base + lane;
            bool in = (idx < nhi) && (sA[idx & SMASK].x >= wLo)
                                  && (sA[idx & SMASK].x <= wHi);
            unsigned m = __ballot_sync(FULLM, in);
            if (m) {
                glo = min(glo, base + (__ffs(m) - 1));
                ghi = max(ghi, base + (31 - __clz(m)) + 1);
            }
        }
        if (ghi < glo) { glo = nlo; ghi = nlo; }

        const float x1n = 0.5f * (x0n + x2n);
        for (int j = nlo + lane; j < nhi; j += 32) {
            if (j >= glo && j < ghi) continue;
            float4 a = sA[j & SMASK];
            float d0 = x0n - a.x, d1 = x1n - a.x, d2 = x2n - a.x;
            float e0 = fmaf(d0, d0, a.y);
            float e1 = fmaf(d1, d1, a.y);
            float e2 = fmaf(d2, d2, a.y);
            float p01 = e0 * e1;
            float r   = frcp(p01 * e2);
            float r01 = r * e2;
            M0 = fmaf(a.z * e1, r01, M0);
            M1 = fmaf(a.z * e0, r01, M1);
            M2 = fmaf(a.z, r * p01, M2);
        }
        #pragma unroll
        for (int o = 16; o; o >>= 1) {
            M0 += __shfl_xor_sync(FULLM, M0, o);
            M1 += __shfl_xor_sync(FULLM, M1, o);
            M2 += __shfl_xor_sync(FULLM, M2, o);
        }

        // warp-near: exact voigt, paired rcp (one per two lines)
        float prodA = 1.0f, prodB = 1.0f;
        int j = glo;
        for (; j + 1 < ghi; j += 2) {
            float4 a0 = sA[j & SMASK];       float cg0 = sB[j & SMASK];
            float4 a1 = sA[(j + 1) & SMASK]; float cg1 = sB[(j + 1) & SMASK];
            float dd0 = wlp - a0.x, dd1 = wlp - a1.x;
            float q0 = dd0 * dd0,   q1 = dd1 * dd1;
            float e0 = q0 + a0.y,   e1 = q1 + a1.y;
            float r  = frcp(e0 * e1);
            float v0 = fmaf(cg0, fex2(q0 * a0.w), (a0.z * e1) * r);
            float v1 = fmaf(cg1, fex2(q1 * a1.w), (a1.z * e0) * r);
            prodA = fmaf(-v0, prodA, prodA);
            prodB = fmaf(-v1, prodB, prodB);
        }
        if (j < ghi) {
            float4 a = sA[j & SMASK]; float cg = sB[j & SMASK];
            float dd = wlp - a.x;
            float q  = dd * dd;
            float v  = fmaf(cg, fex2(q * a.w), a.z * frcp(q + a.y));
            prodA = fmaf(-v, prodA, prodA);
        }
        prod = prodA * prodB;
    }

    __syncthreads();   // sMid, sS visible

    // ---- epilogue ----
    if (tid < cnt && p < npix) {
        const float ic = frcp((float)(cnt - 1));

        float s = (float)tid * (3.0f * ic);
        float sm1 = s - 1.0f, sm2 = s - 2.0f, sm3 = s - 3.0f;
        float Sfar = (sm1 * sm2 * sm3) * (-1.0f / 6.0f) * sS[0]
                   + (s   * sm2 * sm3) * ( 0.5f       ) * sS[1]
                   + (s   * sm1 * sm3) * (-0.5f       ) * sS[2]
                   + (s   * sm1 * sm2) * ( 1.0f / 6.0f) * sS[3];

        float t  = (float)tid * (15.0f * ic);
        int   i  = min(max((int)t, 1), 13);
        float x  = t - (float)i;
        float xp1 = x + 1.0f, xm1 = x - 1.0f, xm2 = x - 2.0f;
        float Smid = (-x   * xm1 * xm2 * (1.0f / 6.0f)) * sMid[i - 1]
                   + ( xp1 * xm1 * xm2 * 0.5f         ) * sMid[i]
                   + (-xp1 * x   * xm2 * 0.5f         ) * sMid[i + 1]
                   + ( xp1 * x   * xm1 * (1.0f / 6.0f)) * sMid[i + 2];

        float hw = 0.5f * (x2n - x0n);
        float u  = (wlp - x0n) * frcp(hw);
        float um1 = u - 1.0f, um2 = u - 2.0f;
        float Swm = (um1 * um2 * 0.5f) * M0
                  + (u * (2.0f - u)  ) * M1
                  + (u * um1 * 0.5f  ) * M2;

        float xw   = (wlp - 10500.0f) * (1.0f / 2500.0f);
        float polw = cpa + (cpb + cpc * xw) * xw;
        out[p] = prod * fex2(-(Sfar + Smid + Swm) * (float)LOG2E) * polw;
    }
}

extern "C" void kernel_launch(void* const* d_in, const int* in_sizes, int n_in,
                              void* d_out, int out_size) {
    const float* wl   = (const float*)d_in[0];
    const float* lam  = (const float*)d_in[1];
    const float* amps = (const float*)d_in[2];
    const float* sw   = (const float*)d_in[3];
    const float* gw   = (const float*)d_in[4];
    const float* pa   = (const float*)d_in[5];
    const float* pb   = (const float*)d_in[6];
    const float* pc   = (const float*)d_in[7];
    float* out = (float*)d_out;

    int npix = in_sizes[0];
    int L    = in_sizes[1];

    int nchunks = (npix + CHUNK - 1) / CHUNK;
    fused_kernel<<<nchunks, BLOCK>>>(wl, npix, L, lam, amps, sw, gw,
                                     pa, pb, pc, out);
}